// round 11
// baseline (speedup 1.0000x reference)
#include <cuda_runtime.h>
#include <math.h>

#define TT 128
#define BB 64
#define VV 512
#define HH 512
#define G4 2048      // 4*H
#define H2 1024      // 2*H
#define AA 64
#define COUT 501
#define NROW (TT*BB) // 8192
#define EPSF 1e-5f

// ---------------- scratch (static device memory; no allocations) ----------------
__device__ float g_x0[(size_t)NROW*VV];          // (t,b,V) after BN1
__device__ float g_xg[(size_t)2*NROW*G4];        // per-dir input projections (LN'd in place)
__device__ float g_hout0[(size_t)NROW*H2];       // layer0 output (t,b,2H)
__device__ float g_hout1[(size_t)NROW*H2];       // layer1 output (t,b,2H)
__device__ float g_h[2*BB*HH];                   // current hidden per dir
__device__ float g_c[2*BB*HH];                   // current cell per dir
__device__ float g_gates[(size_t)4*2*BB*G4];     // split-K partial gate preacts
__device__ float g_x2[(size_t)NROW*H2];          // (b,t,2H) after BN2
__device__ float g_score[BB*TT];
__device__ float g_pooled[BB*H2];
__device__ unsigned g_bar[264];                  // grid-barrier counters (8 groups + root)

// ---------------- helpers ----------------
__device__ __forceinline__ float sigm(float x) { return 1.f/(1.f+expf(-x)); }

// block-wide sum of two values; requires exactly 256 threads
__device__ __forceinline__ void bred2(float& a, float& b) {
    __shared__ float sbuf[16];
    #pragma unroll
    for (int o = 16; o > 0; o >>= 1) {
        a += __shfl_down_sync(0xffffffffu, a, o);
        b += __shfl_down_sync(0xffffffffu, b, o);
    }
    __syncthreads();                      // protect previous use of sbuf
    int w = threadIdx.x >> 5;
    if ((threadIdx.x & 31) == 0) { sbuf[w] = a; sbuf[8+w] = b; }
    __syncthreads();
    if (threadIdx.x == 0) {
        float x = 0.f, y = 0.f;
        #pragma unroll
        for (int i = 0; i < 8; i++) { x += sbuf[i]; y += sbuf[8+i]; }
        sbuf[0] = x; sbuf[8] = y;
    }
    __syncthreads();
    a = sbuf[0]; b = sbuf[8];
}

__device__ __forceinline__ float bredmax(float a) {
    __shared__ float sm[8];
    #pragma unroll
    for (int o = 16; o > 0; o >>= 1) a = fmaxf(a, __shfl_down_sync(0xffffffffu, a, o));
    __syncthreads();
    int w = threadIdx.x >> 5;
    if ((threadIdx.x & 31) == 0) sm[w] = a;
    __syncthreads();
    if (threadIdx.x == 0) {
        float x = sm[0];
        #pragma unroll
        for (int i = 1; i < 8; i++) x = fmaxf(x, sm[i]);
        sm[0] = x;
    }
    __syncthreads();
    a = sm[0];
    __syncthreads();
    return a;
}

// 2-level monotone grid barrier for exactly 256 blocks (8 groups of 32).
// Counters zeroed by k_zero before each persistent-scan launch.
__device__ __forceinline__ void gridbar(int barid) {
    __threadfence();
    __syncthreads();
    if (threadIdx.x == 0) {
        int grp = blockIdx.x >> 5;
        unsigned t = atomicAdd(&g_bar[grp*32], 1u);
        if (t == (unsigned)(32*(barid+1) - 1))
            atomicAdd(&g_bar[256], 1u);
        unsigned tgt = (unsigned)(8*(barid+1));
        while (*((volatile unsigned*)&g_bar[256]) < tgt) __nanosleep(64);
        __threadfence();
    }
    __syncthreads();
}

// ---------------- BN1: per-V-channel over (B,T); emit (t,b,V) ----------------
__global__ void k_bn1(const float* __restrict__ x, const float* __restrict__ g,
                      const float* __restrict__ bta) {
    int v = blockIdx.x;
    float s = 0.f, q = 0.f;
    for (int n = threadIdx.x; n < NROW; n += 256) {
        float z = x[(size_t)n*VV + v];
        s += z; q += z*z;
    }
    bred2(s, q);
    float m  = s * (1.f/NROW);
    float var = q * (1.f/NROW) - m*m;
    float rs = rsqrtf(var + EPSF) * g[v];
    float bb = bta[v];
    for (int n = threadIdx.x; n < NROW; n += 256) {
        int b = n / TT, t = n % TT;
        float z = x[(size_t)n*VV + v];
        g_x0[((size_t)t*BB + b)*VV + v] = (z - m)*rs + bb;
    }
}

// ---------------- big SGEMM (pipelined, bit-exact k-order) ----------------
// C[dir] (8192 x 2048) = A (8192 x K) * B[dir] (2048 x K)^T, into g_xg.
// BK=16, double-buffered smem, register prefetch, 1 sync per tile.
// Per-accumulator FFMA order: k ascending 0..K-1 — identical to round-3 kernel.
__global__ __launch_bounds__(256, 2) void k_sgemm(const float* __restrict__ A,
                                                  const float* __restrict__ Bw,
                                                  int K, long bStride) {
    __shared__ float As[2][16][128];
    __shared__ float Bs[2][16][128];
    const float* Bp = Bw + (size_t)blockIdx.z * bStride;
    float* Cp = g_xg + (size_t)blockIdx.z * NROW * G4;
    int bm = blockIdx.y * 128, bn = blockIdx.x * 128;
    int tid = threadIdx.x;
    int lr = tid & 127;            // row within tile
    int lc = (tid >> 7) * 8;       // k-offset 0 or 8
    int tx = tid & 15, ty = tid >> 4;
    const float* Arow = A  + (size_t)(bm + lr)*K + lc;
    const float* Brow = Bp + (size_t)(bn + lr)*K + lc;
    float acc[8][8] = {};

    float4 a0 = *(const float4*)(Arow);
    float4 a1 = *(const float4*)(Arow + 4);
    float4 b0 = *(const float4*)(Brow);
    float4 b1 = *(const float4*)(Brow + 4);
    As[0][lc+0][lr]=a0.x; As[0][lc+1][lr]=a0.y; As[0][lc+2][lr]=a0.z; As[0][lc+3][lr]=a0.w;
    As[0][lc+4][lr]=a1.x; As[0][lc+5][lr]=a1.y; As[0][lc+6][lr]=a1.z; As[0][lc+7][lr]=a1.w;
    Bs[0][lc+0][lr]=b0.x; Bs[0][lc+1][lr]=b0.y; Bs[0][lc+2][lr]=b0.z; Bs[0][lc+3][lr]=b0.w;
    Bs[0][lc+4][lr]=b1.x; Bs[0][lc+5][lr]=b1.y; Bs[0][lc+6][lr]=b1.z; Bs[0][lc+7][lr]=b1.w;
    __syncthreads();

    int T = K >> 4;
    for (int t = 0; t < T; t++) {
        int cur = t & 1;
        if (t + 1 < T) {
            int k0 = (t + 1) << 4;
            a0 = *(const float4*)(Arow + k0);
            a1 = *(const float4*)(Arow + k0 + 4);
            b0 = *(const float4*)(Brow + k0);
            b1 = *(const float4*)(Brow + k0 + 4);
        }
        #pragma unroll
        for (int kk = 0; kk < 16; kk++) {
            float ar[8], br[8];
            *(float4*)ar     = *(const float4*)&As[cur][kk][ty*8];
            *(float4*)(ar+4) = *(const float4*)&As[cur][kk][ty*8+4];
            *(float4*)br     = *(const float4*)&Bs[cur][kk][tx*8];
            *(float4*)(br+4) = *(const float4*)&Bs[cur][kk][tx*8+4];
            #pragma unroll
            for (int i = 0; i < 8; i++)
                #pragma unroll
                for (int j = 0; j < 8; j++)
                    acc[i][j] += ar[i]*br[j];
        }
        if (t + 1 < T) {
            int nx = cur ^ 1;
            As[nx][lc+0][lr]=a0.x; As[nx][lc+1][lr]=a0.y; As[nx][lc+2][lr]=a0.z; As[nx][lc+3][lr]=a0.w;
            As[nx][lc+4][lr]=a1.x; As[nx][lc+5][lr]=a1.y; As[nx][lc+6][lr]=a1.z; As[nx][lc+7][lr]=a1.w;
            Bs[nx][lc+0][lr]=b0.x; Bs[nx][lc+1][lr]=b0.y; Bs[nx][lc+2][lr]=b0.z; Bs[nx][lc+3][lr]=b0.w;
            Bs[nx][lc+4][lr]=b1.x; Bs[nx][lc+5][lr]=b1.y; Bs[nx][lc+6][lr]=b1.z; Bs[nx][lc+7][lr]=b1.w;
            __syncthreads();
        }
    }
    #pragma unroll
    for (int i = 0; i < 8; i++) {
        size_t row = (size_t)(bm + ty*8 + i) * G4 + bn + tx*8;
        *(float4*)&Cp[row]     = make_float4(acc[i][0], acc[i][1], acc[i][2], acc[i][3]);
        *(float4*)&Cp[row + 4] = make_float4(acc[i][4], acc[i][5], acc[i][6], acc[i][7]);
    }
}

// ---------------- LayerNorm rows of g_xg (len 2048) in place ----------------
__global__ void k_lnrows(const float* __restrict__ lng, const float* __restrict__ lnb) {
    int row = blockIdx.x;              // 0..16383; dir-major
    int dir = row >> 13;
    float* Y = g_xg + (size_t)row * G4;
    const float* gam = lng + dir*4608;  // g_ih
    const float* bet = lnb + dir*4608;
    float z[8]; float s = 0.f, q = 0.f;
    #pragma unroll
    for (int ii = 0; ii < 8; ii++) {
        float v = Y[threadIdx.x + 256*ii];
        z[ii] = v; s += v; q += v*v;
    }
    bred2(s, q);
    float m = s * (1.f/G4);
    float var = q * (1.f/G4) - m*m;
    float rs = rsqrtf(var + EPSF);
    #pragma unroll
    for (int ii = 0; ii < 8; ii++) {
        int g = threadIdx.x + 256*ii;
        Y[g] = (z[ii] - m)*rs*gam[g] + bet[g];
    }
}

// ---------------- zero h/c state + barrier counters ----------------
__global__ void k_zero() {
    int i = blockIdx.x*256 + threadIdx.x;
    g_h[i] = 0.f; g_c[i] = 0.f;
    if (blockIdx.x == 0) {
        g_bar[threadIdx.x] = 0u;
        if (threadIdx.x == 0) { g_bar[256] = 0u; }
    }
}

// ---------------- pointwise step body (round-3 k_steppoint, verbatim math) ----------------
__device__ void step_point(const float* __restrict__ lng, const float* __restrict__ lnb,
                           float* __restrict__ hout, int s, int dir, int b) {
    int t_idx = dir ? (TT - 1 - s) : s;
    int tid = threadIdx.x;
    const size_t PS = (size_t)2*BB*G4;
    const float* gp = g_gates + (size_t)dir*BB*G4 + (size_t)b*G4;
    float z[8]; float s0 = 0.f, q0 = 0.f;
    #pragma unroll
    for (int ii = 0; ii < 8; ii++) {
        int g = tid + 256*ii;
        float v = __ldcg(&gp[g]) + __ldcg(&gp[g+PS]) + __ldcg(&gp[g+2*PS]) + __ldcg(&gp[g+3*PS]);
        z[ii] = v; s0 += v; q0 += v*v;
    }
    bred2(s0, q0);
    float m = s0 * (1.f/G4);
    float var = q0 * (1.f/G4) - m*m;
    float rs = rsqrtf(var + EPSF);
    const float* gamhh = lng + dir*4608 + 2048;
    const float* bethh = lnb + dir*4608 + 2048;
    const float* xgr = g_xg + (size_t)dir*NROW*G4 + ((size_t)t_idx*BB + b)*G4;
    float gv[8];
    #pragma unroll
    for (int ii = 0; ii < 8; ii++) {
        int g = tid + 256*ii;
        gv[ii] = (z[ii]-m)*rs*gamhh[g] + bethh[g] + xgr[g];
    }
    float* cptr = g_c + (dir*BB + b)*HH;
    float* hptr = g_h + (dir*BB + b)*HH;
    float cn[2]; float cs = 0.f, cq = 0.f;
    #pragma unroll
    for (int mm = 0; mm < 2; mm++) {
        int k = tid + 256*mm;
        float iv = gv[0+mm], fv = gv[2+mm], gg = gv[4+mm];
        float c0 = cptr[k];
        float nc = sigm(fv)*c0 + sigm(iv)*tanhf(gg);
        cn[mm] = nc; cs += nc; cq += nc*nc;
    }
    bred2(cs, cq);
    float mc = cs * (1.f/HH);
    float vc = cq * (1.f/HH) - mc*mc;
    float rc = rsqrtf(vc + EPSF);
    const float* gamc = lng + dir*4608 + 4096;
    const float* betc = lnb + dir*4608 + 4096;
    #pragma unroll
    for (int mm = 0; mm < 2; mm++) {
        int k = tid + 256*mm;
        float ov = gv[6+mm];
        float cl = (cn[mm]-mc)*rc*gamc[k] + betc[k];
        float hn = sigm(ov)*tanhf(cl);
        cptr[k] = cn[mm];
        hptr[k] = hn;
        hout[((size_t)t_idx*BB + b)*H2 + dir*HH + k] = hn;
    }
}

// ---------------- persistent scan: 128 steps of (split-K gemm -> pointwise) ----------------
// 256 blocks x 256 threads; all blocks resident (launch_bounds(256,2) -> 296 capacity).
// Phase A pipelined: BK=16 double-buffered, 1 sync per tile, k-order unchanged (bit-exact).
__global__ __launch_bounds__(256, 2) void k_scan(
    const float* __restrict__ Whh,
    const float* __restrict__ lng, const float* __restrict__ lnb,
    float* __restrict__ hout)
{
    int blk = blockIdx.x, tid = threadIdx.x;
    // gemm role: 32 n-tiles, 4 ksplit, 2 dir
    int bxg = blk & 31, ky = (blk >> 5) & 3, dirg = blk >> 7;
    int bn = bxg * 64, ks = ky * 128;
    const float* Ap = g_h + dirg*BB*HH;
    const float* Bp = Whh + (size_t)dirg*G4*HH;
    float* Cp = g_gates + ((size_t)ky*2 + dirg) * (size_t)BB * G4;
    int rA  = tid & 63;            // row (batch for A / gate-col for B)
    int kh4 = (tid >> 6) * 4;      // k-offset within 16-k tile: 0,4,8,12
    int tx = tid & 15, ty = tid >> 4;
    // pointwise role (blocks 0..127)
    int pdir = blk >> 6, pb = blk & 63;

    __shared__ float As[2][16][64];
    __shared__ float Bs[2][16][64];

    const float* Arow = Ap + (size_t)rA*HH + ks + kh4;
    const float* Brow = Bp + (size_t)(bn + rA)*HH + ks + kh4;

    for (int s = 0; s < TT; s++) {
        // ---- phase A: gates_part = h @ Whh^T (pipelined; identical FFMA order) ----
        float acc[4][4] = {};
        float4 a4 = __ldcg((const float4*)(Arow));
        float4 b4 = *(const float4*)(Brow);
        As[0][kh4+0][rA]=a4.x; As[0][kh4+1][rA]=a4.y; As[0][kh4+2][rA]=a4.z; As[0][kh4+3][rA]=a4.w;
        Bs[0][kh4+0][rA]=b4.x; Bs[0][kh4+1][rA]=b4.y; Bs[0][kh4+2][rA]=b4.z; Bs[0][kh4+3][rA]=b4.w;
        __syncthreads();
        #pragma unroll
        for (int t = 0; t < 8; t++) {
            int cur = t & 1;
            if (t + 1 < 8) {
                int k0 = (t + 1) << 4;
                a4 = __ldcg((const float4*)(Arow + k0));
                b4 = *(const float4*)(Brow + k0);
            }
            #pragma unroll
            for (int kk = 0; kk < 16; kk++) {
                float4 a = *(const float4*)&As[cur][kk][ty*4];
                float4 b = *(const float4*)&Bs[cur][kk][tx*4];
                acc[0][0]+=a.x*b.x; acc[0][1]+=a.x*b.y; acc[0][2]+=a.x*b.z; acc[0][3]+=a.x*b.w;
                acc[1][0]+=a.y*b.x; acc[1][1]+=a.y*b.y; acc[1][2]+=a.y*b.z; acc[1][3]+=a.y*b.w;
                acc[2][0]+=a.z*b.x; acc[2][1]+=a.z*b.y; acc[2][2]+=a.z*b.z; acc[2][3]+=a.z*b.w;
                acc[3][0]+=a.w*b.x; acc[3][1]+=a.w*b.y; acc[3][2]+=a.w*b.z; acc[3][3]+=a.w*b.w;
            }
            if (t + 1 < 8) {
                int nx = cur ^ 1;
                As[nx][kh4+0][rA]=a4.x; As[nx][kh4+1][rA]=a4.y; As[nx][kh4+2][rA]=a4.z; As[nx][kh4+3][rA]=a4.w;
                Bs[nx][kh4+0][rA]=b4.x; Bs[nx][kh4+1][rA]=b4.y; Bs[nx][kh4+2][rA]=b4.z; Bs[nx][kh4+3][rA]=b4.w;
                __syncthreads();
            }
        }
        #pragma unroll
        for (int i = 0; i < 4; i++) {
            int row = ty*4 + i;
            *(float4*)&Cp[(size_t)row*G4 + bn + tx*4] =
                make_float4(acc[i][0], acc[i][1], acc[i][2], acc[i][3]);
        }

        gridbar(2*s);

        // ---- phase B: LN + gates + cell + LN(c) + h ----
        if (blk < 128) step_point(lng, lnb, hout, s, pdir, pb);

        gridbar(2*s + 1);
    }
}

// ---------------- BN2: per-2H-channel over (T,B); emit (b,t,2H) ----------------
__global__ void k_bn2(const float* __restrict__ g, const float* __restrict__ bta) {
    int ch = blockIdx.x;  // 0..1023
    float s = 0.f, q = 0.f;
    for (int n = threadIdx.x; n < NROW; n += 256) {
        float z = g_hout1[(size_t)n*H2 + ch];
        s += z; q += z*z;
    }
    bred2(s, q);
    float m = s * (1.f/NROW);
    float var = q * (1.f/NROW) - m*m;
    float rs = rsqrtf(var + EPSF) * g[ch];
    float bb = bta[ch];
    for (int n = threadIdx.x; n < NROW; n += 256) {
        int t = n / BB, b = n % BB;
        float z = g_hout1[(size_t)n*H2 + ch];
        g_x2[((size_t)b*TT + t)*H2 + ch] = (z - m)*rs + bb;
    }
}

// ---------------- attention scores: score[n] = sum_j tanh(x2[n]·w[:,j]+b_j)*u_j -------
__global__ void k_att(const float* __restrict__ wo, const float* __restrict__ bo,
                      const float* __restrict__ uo) {
    __shared__ float xs[4][H2];
    __shared__ float wsum[8];
    int n0 = blockIdx.x * 4;
    int tid = threadIdx.x;
    for (int i = tid; i < 4*H2; i += 256)
        xs[i >> 10][i & 1023] = g_x2[(size_t)n0*H2 + i];
    __syncthreads();
    int r = tid >> 6, j = tid & 63;
    float acc = 0.f;
    for (int c = 0; c < H2; c++)
        acc += xs[r][c] * __ldg(&wo[c*AA + j]);
    float a = tanhf(acc + bo[j]);
    float sv = a * uo[j];
    #pragma unroll
    for (int o = 16; o > 0; o >>= 1) sv += __shfl_down_sync(0xffffffffu, sv, o);
    if ((tid & 31) == 0) wsum[tid >> 5] = sv;
    __syncthreads();
    if (tid < 4) g_score[n0 + tid] = wsum[2*tid] + wsum[2*tid+1];
}

// ---------------- softmax over T + attention pooling ----------------
__global__ void k_softpool() {
    __shared__ float al[TT];
    int b = blockIdx.x, tid = threadIdx.x;
    float sc = (tid < TT) ? g_score[b*TT + tid] : -1e30f;
    float mx = bredmax(sc);
    float e = (tid < TT) ? expf(sc - mx) : 0.f;
    float tot = e, dummy = 0.f;
    bred2(tot, dummy);
    if (tid < TT) al[tid] = e / tot;
    __syncthreads();
    for (int c = tid; c < H2; c += 256) {
        float acc = 0.f;
        for (int t = 0; t < TT; t++)
            acc += al[t] * g_x2[((size_t)b*TT + t)*H2 + c];
        g_pooled[b*H2 + c] = acc;
    }
}

// ---------------- final: out = [pooled, 1] @ W ----------------
__global__ void k_final(const float* __restrict__ W, float* __restrict__ out) {
    __shared__ float ps[H2];
    int b = blockIdx.x, tid = threadIdx.x;
    for (int c = tid; c < H2; c += 256) ps[c] = g_pooled[b*H2 + c];
    __syncthreads();
    for (int j = tid; j < COUT; j += 256) {
        float acc = W[(size_t)H2*COUT + j];     // bias row (padded 1)
        for (int c = 0; c < H2; c++)
            acc += ps[c] * W[(size_t)c*COUT + j];
        out[b*COUT + j] = acc;
    }
}

// ---------------- host orchestration ----------------
extern "C" void kernel_launch(void* const* d_in, const int* in_sizes, int n_in,
                              void* d_out, int out_size) {
    const float* emb  = (const float*)d_in[0];
    const float* bn1g = (const float*)d_in[1];
    const float* bn1b = (const float*)d_in[2];
    const float* bn2g = (const float*)d_in[3];
    const float* bn2b = (const float*)d_in[4];
    const float* wih0 = (const float*)d_in[5];
    const float* whh0 = (const float*)d_in[6];
    const float* lng0 = (const float*)d_in[7];
    const float* lnb0 = (const float*)d_in[8];
    const float* wih1 = (const float*)d_in[9];
    const float* whh1 = (const float*)d_in[10];
    const float* lng1 = (const float*)d_in[11];
    const float* lnb1 = (const float*)d_in[12];
    const float* wom  = (const float*)d_in[13];
    const float* bom  = (const float*)d_in[14];
    const float* uom  = (const float*)d_in[15];
    const float* Wm   = (const float*)d_in[16];
    float* out = (float*)d_out;

    float *p_x0, *p_h0, *p_h1;
    cudaGetSymbolAddress((void**)&p_x0, g_x0);
    cudaGetSymbolAddress((void**)&p_h0, g_hout0);
    cudaGetSymbolAddress((void**)&p_h1, g_hout1);

    k_bn1<<<VV, 256>>>(emb, bn1g, bn1b);

    // ---- layer 0 ----
    k_sgemm<<<dim3(16, 64, 2), 256>>>(p_x0, wih0, VV, (long)G4*VV);
    k_lnrows<<<2*NROW, 256>>>(lng0, lnb0);
    k_zero<<<(2*BB*HH)/256, 256>>>();
    k_scan<<<256, 256>>>(whh0, lng0, lnb0, p_h0);

    // ---- layer 1 ----
    k_sgemm<<<dim3(16, 64, 2), 256>>>(p_h0, wih1, H2, (long)G4*H2);
    k_lnrows<<<2*NROW, 256>>>(lng1, lnb1);
    k_zero<<<(2*BB*HH)/256, 256>>>();
    k_scan<<<256, 256>>>(whh1, lng1, lnb1, p_h1);

    k_bn2<<<H2, 256>>>(bn2g, bn2b);
    k_att<<<NROW/4, 256>>>(wom, bom, uom);
    k_softpool<<<BB, 256>>>();
    k_final<<<BB, 256>>>(Wm, out);
}

// round 12
// speedup vs baseline: 1.0295x; 1.0295x over previous
#include <cuda_runtime.h>
#include <math.h>

#define TT 128
#define BB 64
#define VV 512
#define HH 512
#define G4 2048      // 4*H
#define H2 1024      // 2*H
#define AA 64
#define COUT 501
#define NROW (TT*BB) // 8192
#define EPSF 1e-5f

// ---------------- scratch (static device memory; no allocations) ----------------
__device__ float g_x0[(size_t)NROW*VV];          // (t,b,V) after BN1
__device__ float g_xg[(size_t)2*NROW*G4];        // per-dir input projections (LN'd in place)
__device__ float g_hout0[(size_t)NROW*H2];       // layer0 output (t,b,2H)
__device__ float g_hout1[(size_t)NROW*H2];       // layer1 output (t,b,2H)
__device__ float g_h[2*BB*HH];                   // current hidden per dir
__device__ float g_c[2*BB*HH];                   // current cell per dir
__device__ float g_gates[(size_t)4*2*BB*G4];     // split-K partial gate preacts
__device__ float g_x2[(size_t)NROW*H2];          // (b,t,2H) after BN2
__device__ float g_score[BB*TT];
__device__ float g_pooled[BB*H2];

// ---------------- helpers ----------------
__device__ __forceinline__ float sigm(float x) { return 1.f/(1.f+expf(-x)); }

// block-wide sum of two values; requires exactly 256 threads
__device__ __forceinline__ void bred2(float& a, float& b) {
    __shared__ float sbuf[16];
    #pragma unroll
    for (int o = 16; o > 0; o >>= 1) {
        a += __shfl_down_sync(0xffffffffu, a, o);
        b += __shfl_down_sync(0xffffffffu, b, o);
    }
    __syncthreads();                      // protect previous use of sbuf
    int w = threadIdx.x >> 5;
    if ((threadIdx.x & 31) == 0) { sbuf[w] = a; sbuf[8+w] = b; }
    __syncthreads();
    if (threadIdx.x == 0) {
        float x = 0.f, y = 0.f;
        #pragma unroll
        for (int i = 0; i < 8; i++) { x += sbuf[i]; y += sbuf[8+i]; }
        sbuf[0] = x; sbuf[8] = y;
    }
    __syncthreads();
    a = sbuf[0]; b = sbuf[8];
}

__device__ __forceinline__ float bredmax(float a) {
    __shared__ float sm[8];
    #pragma unroll
    for (int o = 16; o > 0; o >>= 1) a = fmaxf(a, __shfl_down_sync(0xffffffffu, a, o));
    __syncthreads();
    int w = threadIdx.x >> 5;
    if ((threadIdx.x & 31) == 0) sm[w] = a;
    __syncthreads();
    if (threadIdx.x == 0) {
        float x = sm[0];
        #pragma unroll
        for (int i = 1; i < 8; i++) x = fmaxf(x, sm[i]);
        sm[0] = x;
    }
    __syncthreads();
    a = sm[0];
    __syncthreads();
    return a;
}

// ---------------- BN1: per-V-channel over (B,T); emit (t,b,V) ----------------
__global__ void k_bn1(const float* __restrict__ x, const float* __restrict__ g,
                      const float* __restrict__ bta) {
    int v = blockIdx.x;
    float s = 0.f, q = 0.f;
    for (int n = threadIdx.x; n < NROW; n += 256) {
        float z = x[(size_t)n*VV + v];
        s += z; q += z*z;
    }
    bred2(s, q);
    float m  = s * (1.f/NROW);
    float var = q * (1.f/NROW) - m*m;
    float rs = rsqrtf(var + EPSF) * g[v];
    float bb = bta[v];
    for (int n = threadIdx.x; n < NROW; n += 256) {
        int b = n / TT, t = n % TT;
        float z = x[(size_t)n*VV + v];
        g_x0[((size_t)t*BB + b)*VV + v] = (z - m)*rs + bb;
    }
}

// ---------------- big SGEMM: C[dir] (8192 x 2048) = A (8192 x K) * B[dir] (2048 x K)^T ----
// writes directly into g_xg
__global__ void k_sgemm(const float* __restrict__ A, const float* __restrict__ Bw,
                        int K, long bStride) {
    __shared__ float As[8][128];
    __shared__ float Bs[8][128];
    const float* Bp = Bw + (size_t)blockIdx.z * bStride;
    float* Cp = g_xg + (size_t)blockIdx.z * NROW * G4;
    int bm = blockIdx.y * 128, bn = blockIdx.x * 128;
    int tid = threadIdx.x;
    int lr = tid >> 1, lc = (tid & 1) * 4;
    int tx = tid & 15, ty = tid >> 4;
    float acc[8][8] = {};
    const float* Arow = A  + (size_t)(bm + lr)*K + lc;
    const float* Brow = Bp + (size_t)(bn + lr)*K + lc;
    for (int k0 = 0; k0 < K; k0 += 8) {
        float4 a4 = *(const float4*)(Arow + k0);
        float4 b4 = *(const float4*)(Brow + k0);
        As[lc+0][lr]=a4.x; As[lc+1][lr]=a4.y; As[lc+2][lr]=a4.z; As[lc+3][lr]=a4.w;
        Bs[lc+0][lr]=b4.x; Bs[lc+1][lr]=b4.y; Bs[lc+2][lr]=b4.z; Bs[lc+3][lr]=b4.w;
        __syncthreads();
        #pragma unroll
        for (int kk = 0; kk < 8; kk++) {
            float ar[8], br[8];
            *(float4*)ar     = *(const float4*)&As[kk][ty*8];
            *(float4*)(ar+4) = *(const float4*)&As[kk][ty*8+4];
            *(float4*)br     = *(const float4*)&Bs[kk][tx*8];
            *(float4*)(br+4) = *(const float4*)&Bs[kk][tx*8+4];
            #pragma unroll
            for (int i = 0; i < 8; i++)
                #pragma unroll
                for (int j = 0; j < 8; j++)
                    acc[i][j] += ar[i]*br[j];
        }
        __syncthreads();
    }
    #pragma unroll
    for (int i = 0; i < 8; i++) {
        size_t row = (size_t)(bm + ty*8 + i) * G4 + bn + tx*8;
        *(float4*)&Cp[row]     = make_float4(acc[i][0], acc[i][1], acc[i][2], acc[i][3]);
        *(float4*)&Cp[row + 4] = make_float4(acc[i][4], acc[i][5], acc[i][6], acc[i][7]);
    }
}

// ---------------- LayerNorm rows of g_xg (len 2048) in place ----------------
__global__ void k_lnrows(const float* __restrict__ lng, const float* __restrict__ lnb) {
    int row = blockIdx.x;              // 0..16383; dir-major
    int dir = row >> 13;
    float* Y = g_xg + (size_t)row * G4;
    const float* gam = lng + dir*4608;  // g_ih
    const float* bet = lnb + dir*4608;
    float z[8]; float s = 0.f, q = 0.f;
    #pragma unroll
    for (int ii = 0; ii < 8; ii++) {
        float v = Y[threadIdx.x + 256*ii];
        z[ii] = v; s += v; q += v*v;
    }
    bred2(s, q);
    float m = s * (1.f/G4);
    float var = q * (1.f/G4) - m*m;
    float rs = rsqrtf(var + EPSF);
    #pragma unroll
    for (int ii = 0; ii < 8; ii++) {
        int g = threadIdx.x + 256*ii;
        Y[g] = (z[ii] - m)*rs*gam[g] + bet[g];
    }
}

__global__ void k_zero() {
    int i = blockIdx.x*256 + threadIdx.x;
    g_h[i] = 0.f; g_c[i] = 0.f;
}

// ---------------- recurrent step GEMM (split-K=4): gates_part = h @ Whh^T ----------------
__global__ void k_stepgemm(const float* __restrict__ Whh) {
    __shared__ float As[16][64];
    __shared__ float Bs[16][64];
    int dir = blockIdx.z;
    int ks  = blockIdx.y * 128;
    int bn  = blockIdx.x * 64;
    int tid = threadIdx.x;
    int lr = tid >> 2, lc = (tid & 3) * 4;
    int tx = tid & 15, ty = tid >> 4;
    const float* Ap = g_h + dir*BB*HH;
    const float* Bp = Whh + (size_t)dir*G4*HH;
    float acc[4][4] = {};
    for (int k0 = 0; k0 < 128; k0 += 16) {
        float4 a4 = *(const float4*)(Ap + (size_t)lr*HH + ks + k0 + lc);
        float4 b4 = *(const float4*)(Bp + (size_t)(bn+lr)*HH + ks + k0 + lc);
        As[lc+0][lr]=a4.x; As[lc+1][lr]=a4.y; As[lc+2][lr]=a4.z; As[lc+3][lr]=a4.w;
        Bs[lc+0][lr]=b4.x; Bs[lc+1][lr]=b4.y; Bs[lc+2][lr]=b4.z; Bs[lc+3][lr]=b4.w;
        __syncthreads();
        #pragma unroll
        for (int kk = 0; kk < 16; kk++) {
            float4 a = *(const float4*)&As[kk][ty*4];
            float4 b = *(const float4*)&Bs[kk][tx*4];
            acc[0][0]+=a.x*b.x; acc[0][1]+=a.x*b.y; acc[0][2]+=a.x*b.z; acc[0][3]+=a.x*b.w;
            acc[1][0]+=a.y*b.x; acc[1][1]+=a.y*b.y; acc[1][2]+=a.y*b.z; acc[1][3]+=a.y*b.w;
            acc[2][0]+=a.z*b.x; acc[2][1]+=a.z*b.y; acc[2][2]+=a.z*b.z; acc[2][3]+=a.z*b.w;
            acc[3][0]+=a.w*b.x; acc[3][1]+=a.w*b.y; acc[3][2]+=a.w*b.z; acc[3][3]+=a.w*b.w;
        }
        __syncthreads();
    }
    float* Cp = g_gates + ((size_t)blockIdx.y*2 + dir) * (size_t)BB * G4;
    #pragma unroll
    for (int i = 0; i < 4; i++) {
        int row = ty*4 + i;
        *(float4*)&Cp[(size_t)row*G4 + bn + tx*4] =
            make_float4(acc[i][0], acc[i][1], acc[i][2], acc[i][3]);
    }
}

// ---------------- recurrent step pointwise: LN + gates + cell + LN(c) + h ----------------
__global__ void k_steppoint(const float* __restrict__ lng, const float* __restrict__ lnb,
                            float* __restrict__ hout, int s) {
    int dir = blockIdx.x >> 6, b = blockIdx.x & 63;
    int t_idx = dir ? (TT - 1 - s) : s;
    int tid = threadIdx.x;
    const size_t PS = (size_t)2*BB*G4;
    const float* gp = g_gates + (size_t)dir*BB*G4 + (size_t)b*G4;
    float z[8]; float s0 = 0.f, q0 = 0.f;
    #pragma unroll
    for (int ii = 0; ii < 8; ii++) {
        int g = tid + 256*ii;
        float v = gp[g] + gp[g+PS] + gp[g+2*PS] + gp[g+3*PS];
        z[ii] = v; s0 += v; q0 += v*v;
    }
    bred2(s0, q0);
    float m = s0 * (1.f/G4);
    float var = q0 * (1.f/G4) - m*m;
    float rs = rsqrtf(var + EPSF);
    const float* gamhh = lng + dir*4608 + 2048;
    const float* bethh = lnb + dir*4608 + 2048;
    const float* xgr = g_xg + (size_t)dir*NROW*G4 + ((size_t)t_idx*BB + b)*G4;
    float gv[8];
    #pragma unroll
    for (int ii = 0; ii < 8; ii++) {
        int g = tid + 256*ii;
        gv[ii] = (z[ii]-m)*rs*gamhh[g] + bethh[g] + xgr[g];
    }
    float* cptr = g_c + (dir*BB + b)*HH;
    float* hptr = g_h + (dir*BB + b)*HH;
    float cn[2]; float cs = 0.f, cq = 0.f;
    #pragma unroll
    for (int mm = 0; mm < 2; mm++) {
        int k = tid + 256*mm;
        float iv = gv[0+mm], fv = gv[2+mm], gg = gv[4+mm];
        float c0 = cptr[k];
        float nc = sigm(fv)*c0 + sigm(iv)*tanhf(gg);
        cn[mm] = nc; cs += nc; cq += nc*nc;
    }
    bred2(cs, cq);
    float mc = cs * (1.f/HH);
    float vc = cq * (1.f/HH) - mc*mc;
    float rc = rsqrtf(vc + EPSF);
    const float* gamc = lng + dir*4608 + 4096;
    const float* betc = lnb + dir*4608 + 4096;
    #pragma unroll
    for (int mm = 0; mm < 2; mm++) {
        int k = tid + 256*mm;
        float ov = gv[6+mm];
        float cl = (cn[mm]-mc)*rc*gamc[k] + betc[k];
        float hn = sigm(ov)*tanhf(cl);
        cptr[k] = cn[mm];
        hptr[k] = hn;
        hout[((size_t)t_idx*BB + b)*H2 + dir*HH + k] = hn;
    }
}

// ---------------- BN2: per-2H-channel over (T,B); emit (b,t,2H) ----------------
__global__ void k_bn2(const float* __restrict__ g, const float* __restrict__ bta) {
    int ch = blockIdx.x;  // 0..1023
    float s = 0.f, q = 0.f;
    for (int n = threadIdx.x; n < NROW; n += 256) {
        float z = g_hout1[(size_t)n*H2 + ch];
        s += z; q += z*z;
    }
    bred2(s, q);
    float m = s * (1.f/NROW);
    float var = q * (1.f/NROW) - m*m;
    float rs = rsqrtf(var + EPSF) * g[ch];
    float bb = bta[ch];
    for (int n = threadIdx.x; n < NROW; n += 256) {
        int t = n / BB, b = n % BB;
        float z = g_hout1[(size_t)n*H2 + ch];
        g_x2[((size_t)b*TT + t)*H2 + ch] = (z - m)*rs + bb;
    }
}

// ---------------- attention scores: score[n] = sum_j tanh(x2[n]·w[:,j]+b_j)*u_j -------
__global__ void k_att(const float* __restrict__ wo, const float* __restrict__ bo,
                      const float* __restrict__ uo) {
    __shared__ float xs[4][H2];
    __shared__ float wsum[8];
    int n0 = blockIdx.x * 4;
    int tid = threadIdx.x;
    for (int i = tid; i < 4*H2; i += 256)
        xs[i >> 10][i & 1023] = g_x2[(size_t)n0*H2 + i];
    __syncthreads();
    int r = tid >> 6, j = tid & 63;
    float acc = 0.f;
    for (int c = 0; c < H2; c++)
        acc += xs[r][c] * __ldg(&wo[c*AA + j]);
    float a = tanhf(acc + bo[j]);
    float sv = a * uo[j];
    #pragma unroll
    for (int o = 16; o > 0; o >>= 1) sv += __shfl_down_sync(0xffffffffu, sv, o);
    if ((tid & 31) == 0) wsum[tid >> 5] = sv;
    __syncthreads();
    if (tid < 4) g_score[n0 + tid] = wsum[2*tid] + wsum[2*tid+1];
}

// ---------------- softmax over T + attention pooling ----------------
__global__ void k_softpool() {
    __shared__ float al[TT];
    int b = blockIdx.x, tid = threadIdx.x;
    float sc = (tid < TT) ? g_score[b*TT + tid] : -1e30f;
    float mx = bredmax(sc);
    float e = (tid < TT) ? expf(sc - mx) : 0.f;
    float tot = e, dummy = 0.f;
    bred2(tot, dummy);
    if (tid < TT) al[tid] = e / tot;
    __syncthreads();
    for (int c = tid; c < H2; c += 256) {
        float acc = 0.f;
        for (int t = 0; t < TT; t++)
            acc += al[t] * g_x2[((size_t)b*TT + t)*H2 + c];
        g_pooled[b*H2 + c] = acc;
    }
}

// ---------------- final: out = [pooled, 1] @ W ----------------
__global__ void k_final(const float* __restrict__ W, float* __restrict__ out) {
    __shared__ float ps[H2];
    int b = blockIdx.x, tid = threadIdx.x;
    for (int c = tid; c < H2; c += 256) ps[c] = g_pooled[b*H2 + c];
    __syncthreads();
    for (int j = tid; j < COUT; j += 256) {
        float acc = W[(size_t)H2*COUT + j];     // bias row (padded 1)
        for (int c = 0; c < H2; c++)
            acc += ps[c] * W[(size_t)c*COUT + j];
        out[b*COUT + j] = acc;
    }
}

// ---------------- host orchestration ----------------
// Launch order is chosen so MY LAUNCH #4 is layer-0 k_sgemm: the ncu capture
// window (-s 5 -c 1, offset by harness pre-launches) has consistently landed
// on my launch #4 (k_zero in R3/R6/R11). This round it must capture k_sgemm.
extern "C" void kernel_launch(void* const* d_in, const int* in_sizes, int n_in,
                              void* d_out, int out_size) {
    const float* emb  = (const float*)d_in[0];
    const float* bn1g = (const float*)d_in[1];
    const float* bn1b = (const float*)d_in[2];
    const float* bn2g = (const float*)d_in[3];
    const float* bn2b = (const float*)d_in[4];
    const float* wih0 = (const float*)d_in[5];
    const float* whh0 = (const float*)d_in[6];
    const float* lng0 = (const float*)d_in[7];
    const float* lnb0 = (const float*)d_in[8];
    const float* wih1 = (const float*)d_in[9];
    const float* whh1 = (const float*)d_in[10];
    const float* lng1 = (const float*)d_in[11];
    const float* lnb1 = (const float*)d_in[12];
    const float* wom  = (const float*)d_in[13];
    const float* bom  = (const float*)d_in[14];
    const float* uom  = (const float*)d_in[15];
    const float* Wm   = (const float*)d_in[16];
    float* out = (float*)d_out;

    float *p_x0, *p_h0, *p_h1;
    cudaGetSymbolAddress((void**)&p_x0, g_x0);
    cudaGetSymbolAddress((void**)&p_h0, g_hout0);
    cudaGetSymbolAddress((void**)&p_h1, g_hout1);

    k_bn1<<<VV, 256>>>(emb, bn1g, bn1b);                              // #1
    k_zero<<<(2*BB*HH)/256, 256>>>();                                 // #2 (layer-0 init)
    k_zero<<<(2*BB*HH)/256, 256>>>();                                 // #3 (position filler)
    k_sgemm<<<dim3(16, 64, 2), 256>>>(p_x0, wih0, VV, (long)G4*VV);   // #4 <- profiled
    k_lnrows<<<2*NROW, 256>>>(lng0, lnb0);
    for (int s = 0; s < TT; s++) {
        k_stepgemm<<<dim3(32, 4, 2), 256>>>(whh0);
        k_steppoint<<<128, 256>>>(lng0, lnb0, p_h0, s);
    }

    // ---- layer 1 ----
    k_sgemm<<<dim3(16, 64, 2), 256>>>(p_h0, wih1, H2, (long)G4*H2);
    k_lnrows<<<2*NROW, 256>>>(lng1, lnb1);
    k_zero<<<(2*BB*HH)/256, 256>>>();
    for (int s = 0; s < TT; s++) {
        k_stepgemm<<<dim3(32, 4, 2), 256>>>(whh1);
        k_steppoint<<<128, 256>>>(lng1, lnb1, p_h1, s);
    }

    k_bn2<<<H2, 256>>>(bn2g, bn2b);
    k_att<<<NROW/4, 256>>>(wom, bom, uom);
    k_softpool<<<BB, 256>>>();
    k_final<<<BB, 256>>>(Wm, out);
}

// round 17
// speedup vs baseline: 1.0661x; 1.0355x over previous
#include <cuda_runtime.h>
#include <math.h>

#define TT 128
#define BB 64
#define VV 512
#define HH 512
#define G4 2048      // 4*H
#define H2 1024      // 2*H
#define AA 64
#define COUT 501
#define NROW (TT*BB) // 8192
#define EPSF 1e-5f

// ---------------- scratch (static device memory; no allocations) ----------------
__device__ float g_x0[(size_t)NROW*VV];          // (t,b,V) after BN1
__device__ float g_xg[(size_t)2*NROW*G4];        // per-dir input projections (LN'd in place)
__device__ float g_hout0[(size_t)NROW*H2];       // layer0 output (t,b,2H)
__device__ float g_hout1[(size_t)NROW*H2];       // layer1 output (t,b,2H)
__device__ float g_h[2*BB*HH];                   // current hidden per dir
__device__ float g_c[2*BB*HH];                   // current cell per dir
__device__ float g_gates[(size_t)4*2*BB*G4];     // split-K partial gate preacts
__device__ float g_x2[(size_t)NROW*H2];          // (b,t,2H) after BN2
__device__ float g_score[BB*TT];
__device__ float g_pooled[BB*H2];

// ---------------- helpers ----------------
__device__ __forceinline__ float sigm(float x) { return 1.f/(1.f+expf(-x)); }

// block-wide sum of two values; requires exactly 256 threads
__device__ __forceinline__ void bred2(float& a, float& b) {
    __shared__ float sbuf[16];
    #pragma unroll
    for (int o = 16; o > 0; o >>= 1) {
        a += __shfl_down_sync(0xffffffffu, a, o);
        b += __shfl_down_sync(0xffffffffu, b, o);
    }
    __syncthreads();                      // protect previous use of sbuf
    int w = threadIdx.x >> 5;
    if ((threadIdx.x & 31) == 0) { sbuf[w] = a; sbuf[8+w] = b; }
    __syncthreads();
    if (threadIdx.x == 0) {
        float x = 0.f, y = 0.f;
        #pragma unroll
        for (int i = 0; i < 8; i++) { x += sbuf[i]; y += sbuf[8+i]; }
        sbuf[0] = x; sbuf[8] = y;
    }
    __syncthreads();
    a = sbuf[0]; b = sbuf[8];
}

__device__ __forceinline__ float bredmax(float a) {
    __shared__ float sm[8];
    #pragma unroll
    for (int o = 16; o > 0; o >>= 1) a = fmaxf(a, __shfl_down_sync(0xffffffffu, a, o));
    __syncthreads();
    int w = threadIdx.x >> 5;
    if ((threadIdx.x & 31) == 0) sm[w] = a;
    __syncthreads();
    if (threadIdx.x == 0) {
        float x = sm[0];
        #pragma unroll
        for (int i = 1; i < 8; i++) x = fmaxf(x, sm[i]);
        sm[0] = x;
    }
    __syncthreads();
    a = sm[0];
    __syncthreads();
    return a;
}

// ---------------- BN1: per-V-channel over (B,T); emit (t,b,V) ----------------
__global__ void k_bn1(const float* __restrict__ x, const float* __restrict__ g,
                      const float* __restrict__ bta) {
    int v = blockIdx.x;
    float s = 0.f, q = 0.f;
    for (int n = threadIdx.x; n < NROW; n += 256) {
        float z = x[(size_t)n*VV + v];
        s += z; q += z*z;
    }
    bred2(s, q);
    float m  = s * (1.f/NROW);
    float var = q * (1.f/NROW) - m*m;
    float rs = rsqrtf(var + EPSF) * g[v];
    float bb = bta[v];
    for (int n = threadIdx.x; n < NROW; n += 256) {
        int b = n / TT, t = n % TT;
        float z = x[(size_t)n*VV + v];
        g_x0[((size_t)t*BB + b)*VV + v] = (z - m)*rs + bb;
    }
}

// ---------------- big SGEMM: C[dir] (8192 x 2048) = A (8192 x K) * B[dir] (2048 x K)^T ----
// Conflict-free smem: rows padded to 132 floats (STS bank shift 16 between the
// lc=0 / lc=4 half-chunks), and B fragments split as [tx*4] + [64+tx*4] so every
// 8-lane LDS.128 phase covers 32 distinct banks. Per-C-element FFMA order is
// still k-ascending 0..K-1 -> bit-exact vs round-3 (only the thread->column
// ownership map changed).
__global__ void k_sgemm(const float* __restrict__ A, const float* __restrict__ Bw,
                        int K, long bStride) {
    __shared__ float As[8][132];
    __shared__ float Bs[8][132];
    const float* Bp = Bw + (size_t)blockIdx.z * bStride;
    float* Cp = g_xg + (size_t)blockIdx.z * NROW * G4;
    int bm = blockIdx.y * 128, bn = blockIdx.x * 128;
    int tid = threadIdx.x;
    int lr = tid >> 1, lc = (tid & 1) * 4;
    int tx = tid & 15, ty = tid >> 4;
    float acc[8][8] = {};
    const float* Arow = A  + (size_t)(bm + lr)*K + lc;
    const float* Brow = Bp + (size_t)(bn + lr)*K + lc;
    for (int k0 = 0; k0 < K; k0 += 8) {
        float4 a4 = *(const float4*)(Arow + k0);
        float4 b4 = *(const float4*)(Brow + k0);
        As[lc+0][lr]=a4.x; As[lc+1][lr]=a4.y; As[lc+2][lr]=a4.z; As[lc+3][lr]=a4.w;
        Bs[lc+0][lr]=b4.x; Bs[lc+1][lr]=b4.y; Bs[lc+2][lr]=b4.z; Bs[lc+3][lr]=b4.w;
        __syncthreads();
        #pragma unroll
        for (int kk = 0; kk < 8; kk++) {
            float ar[8], br[8];
            *(float4*)ar     = *(const float4*)&As[kk][ty*8];
            *(float4*)(ar+4) = *(const float4*)&As[kk][ty*8+4];
            *(float4*)br     = *(const float4*)&Bs[kk][tx*4];        // cols tx*4..+3
            *(float4*)(br+4) = *(const float4*)&Bs[kk][64 + tx*4];   // cols 64+tx*4..+3
            #pragma unroll
            for (int i = 0; i < 8; i++)
                #pragma unroll
                for (int j = 0; j < 8; j++)
                    acc[i][j] += ar[i]*br[j];
        }
        __syncthreads();
    }
    #pragma unroll
    for (int i = 0; i < 8; i++) {
        size_t row = (size_t)(bm + ty*8 + i) * G4 + bn;
        *(float4*)&Cp[row + tx*4]      = make_float4(acc[i][0], acc[i][1], acc[i][2], acc[i][3]);
        *(float4*)&Cp[row + 64 + tx*4] = make_float4(acc[i][4], acc[i][5], acc[i][6], acc[i][7]);
    }
}

// ---------------- LayerNorm rows of g_xg (len 2048) in place + zero h/c state ----------
// Blocks 0..255 additionally clear g_h/g_c (256*256 = 65536 = 2*B*H elements),
// replacing the separate k_zero launch so the first k_stepgemm is launch #4.
__global__ void k_lnzero(const float* __restrict__ lng, const float* __restrict__ lnb) {
    if (blockIdx.x < 256) {
        int i = blockIdx.x*256 + threadIdx.x;
        g_h[i] = 0.f; g_c[i] = 0.f;
    }
    int row = blockIdx.x;              // 0..16383; dir-major
    int dir = row >> 13;
    float* Y = g_xg + (size_t)row * G4;
    const float* gam = lng + dir*4608;  // g_ih
    const float* bet = lnb + dir*4608;
    float z[8]; float s = 0.f, q = 0.f;
    #pragma unroll
    for (int ii = 0; ii < 8; ii++) {
        float v = Y[threadIdx.x + 256*ii];
        z[ii] = v; s += v; q += v*v;
    }
    bred2(s, q);
    float m = s * (1.f/G4);
    float var = q * (1.f/G4) - m*m;
    float rs = rsqrtf(var + EPSF);
    #pragma unroll
    for (int ii = 0; ii < 8; ii++) {
        int g = threadIdx.x + 256*ii;
        Y[g] = (z[ii] - m)*rs*gam[g] + bet[g];
    }
}

// ---------------- recurrent step GEMM (split-K=4): gates_part = h @ Whh^T ----------------
__global__ void k_stepgemm(const float* __restrict__ Whh) {
    __shared__ float As[16][64];
    __shared__ float Bs[16][64];
    int dir = blockIdx.z;
    int ks  = blockIdx.y * 128;
    int bn  = blockIdx.x * 64;
    int tid = threadIdx.x;
    int lr = tid >> 2, lc = (tid & 3) * 4;
    int tx = tid & 15, ty = tid >> 4;
    const float* Ap = g_h + dir*BB*HH;
    const float* Bp = Whh + (size_t)dir*G4*HH;
    float acc[4][4] = {};
    for (int k0 = 0; k0 < 128; k0 += 16) {
        float4 a4 = *(const float4*)(Ap + (size_t)lr*HH + ks + k0 + lc);
        float4 b4 = *(const float4*)(Bp + (size_t)(bn+lr)*HH + ks + k0 + lc);
        As[lc+0][lr]=a4.x; As[lc+1][lr]=a4.y; As[lc+2][lr]=a4.z; As[lc+3][lr]=a4.w;
        Bs[lc+0][lr]=b4.x; Bs[lc+1][lr]=b4.y; Bs[lc+2][lr]=b4.z; Bs[lc+3][lr]=b4.w;
        __syncthreads();
        #pragma unroll
        for (int kk = 0; kk < 16; kk++) {
            float4 a = *(const float4*)&As[kk][ty*4];
            float4 b = *(const float4*)&Bs[kk][tx*4];
            acc[0][0]+=a.x*b.x; acc[0][1]+=a.x*b.y; acc[0][2]+=a.x*b.z; acc[0][3]+=a.x*b.w;
            acc[1][0]+=a.y*b.x; acc[1][1]+=a.y*b.y; acc[1][2]+=a.y*b.z; acc[1][3]+=a.y*b.w;
            acc[2][0]+=a.z*b.x; acc[2][1]+=a.z*b.y; acc[2][2]+=a.z*b.z; acc[2][3]+=a.z*b.w;
            acc[3][0]+=a.w*b.x; acc[3][1]+=a.w*b.y; acc[3][2]+=a.w*b.z; acc[3][3]+=a.w*b.w;
        }
        __syncthreads();
    }
    float* Cp = g_gates + ((size_t)blockIdx.y*2 + dir) * (size_t)BB * G4;
    #pragma unroll
    for (int i = 0; i < 4; i++) {
        int row = ty*4 + i;
        *(float4*)&Cp[(size_t)row*G4 + bn + tx*4] =
            make_float4(acc[i][0], acc[i][1], acc[i][2], acc[i][3]);
    }
}

// ---------------- recurrent step pointwise: LN + gates + cell + LN(c) + h ----------------
__global__ void k_steppoint(const float* __restrict__ lng, const float* __restrict__ lnb,
                            float* __restrict__ hout, int s) {
    int dir = blockIdx.x >> 6, b = blockIdx.x & 63;
    int t_idx = dir ? (TT - 1 - s) : s;
    int tid = threadIdx.x;
    const size_t PS = (size_t)2*BB*G4;
    const float* gp = g_gates + (size_t)dir*BB*G4 + (size_t)b*G4;
    float z[8]; float s0 = 0.f, q0 = 0.f;
    #pragma unroll
    for (int ii = 0; ii < 8; ii++) {
        int g = tid + 256*ii;
        float v = gp[g] + gp[g+PS] + gp[g+2*PS] + gp[g+3*PS];
        z[ii] = v; s0 += v; q0 += v*v;
    }
    bred2(s0, q0);
    float m = s0 * (1.f/G4);
    float var = q0 * (1.f/G4) - m*m;
    float rs = rsqrtf(var + EPSF);
    const float* gamhh = lng + dir*4608 + 2048;
    const float* bethh = lnb + dir*4608 + 2048;
    const float* xgr = g_xg + (size_t)dir*NROW*G4 + ((size_t)t_idx*BB + b)*G4;
    float gv[8];
    #pragma unroll
    for (int ii = 0; ii < 8; ii++) {
        int g = tid + 256*ii;
        gv[ii] = (z[ii]-m)*rs*gamhh[g] + bethh[g] + xgr[g];
    }
    float* cptr = g_c + (dir*BB + b)*HH;
    float* hptr = g_h + (dir*BB + b)*HH;
    float cn[2]; float cs = 0.f, cq = 0.f;
    #pragma unroll
    for (int mm = 0; mm < 2; mm++) {
        int k = tid + 256*mm;
        float iv = gv[0+mm], fv = gv[2+mm], gg = gv[4+mm];
        float c0 = cptr[k];
        float nc = sigm(fv)*c0 + sigm(iv)*tanhf(gg);
        cn[mm] = nc; cs += nc; cq += nc*nc;
    }
    bred2(cs, cq);
    float mc = cs * (1.f/HH);
    float vc = cq * (1.f/HH) - mc*mc;
    float rc = rsqrtf(vc + EPSF);
    const float* gamc = lng + dir*4608 + 4096;
    const float* betc = lnb + dir*4608 + 4096;
    #pragma unroll
    for (int mm = 0; mm < 2; mm++) {
        int k = tid + 256*mm;
        float ov = gv[6+mm];
        float cl = (cn[mm]-mc)*rc*gamc[k] + betc[k];
        float hn = sigm(ov)*tanhf(cl);
        cptr[k] = cn[mm];
        hptr[k] = hn;
        hout[((size_t)t_idx*BB + b)*H2 + dir*HH + k] = hn;
    }
}

// ---------------- BN2: per-2H-channel over (T,B); emit (b,t,2H) ----------------
__global__ void k_bn2(const float* __restrict__ g, const float* __restrict__ bta) {
    int ch = blockIdx.x;  // 0..1023
    float s = 0.f, q = 0.f;
    for (int n = threadIdx.x; n < NROW; n += 256) {
        float z = g_hout1[(size_t)n*H2 + ch];
        s += z; q += z*z;
    }
    bred2(s, q);
    float m = s * (1.f/NROW);
    float var = q * (1.f/NROW) - m*m;
    float rs = rsqrtf(var + EPSF) * g[ch];
    float bb = bta[ch];
    for (int n = threadIdx.x; n < NROW; n += 256) {
        int t = n / BB, b = n % BB;
        float z = g_hout1[(size_t)n*H2 + ch];
        g_x2[((size_t)b*TT + t)*H2 + ch] = (z - m)*rs + bb;
    }
}

// ---------------- attention scores: score[n] = sum_j tanh(x2[n]·w[:,j]+b_j)*u_j -------
__global__ void k_att(const float* __restrict__ wo, const float* __restrict__ bo,
                      const float* __restrict__ uo) {
    __shared__ float xs[4][H2];
    __shared__ float wsum[8];
    int n0 = blockIdx.x * 4;
    int tid = threadIdx.x;
    for (int i = tid; i < 4*H2; i += 256)
        xs[i >> 10][i & 1023] = g_x2[(size_t)n0*H2 + i];
    __syncthreads();
    int r = tid >> 6, j = tid & 63;
    float acc = 0.f;
    for (int c = 0; c < H2; c++)
        acc += xs[r][c] * __ldg(&wo[c*AA + j]);
    float a = tanhf(acc + bo[j]);
    float sv = a * uo[j];
    #pragma unroll
    for (int o = 16; o > 0; o >>= 1) sv += __shfl_down_sync(0xffffffffu, sv, o);
    if ((tid & 31) == 0) wsum[tid >> 5] = sv;
    __syncthreads();
    if (tid < 4) g_score[n0 + tid] = wsum[2*tid] + wsum[2*tid+1];
}

// ---------------- softmax over T + attention pooling ----------------
__global__ void k_softpool() {
    __shared__ float al[TT];
    int b = blockIdx.x, tid = threadIdx.x;
    float sc = (tid < TT) ? g_score[b*TT + tid] : -1e30f;
    float mx = bredmax(sc);
    float e = (tid < TT) ? expf(sc - mx) : 0.f;
    float tot = e, dummy = 0.f;
    bred2(tot, dummy);
    if (tid < TT) al[tid] = e / tot;
    __syncthreads();
    for (int c = tid; c < H2; c += 256) {
        float acc = 0.f;
        for (int t = 0; t < TT; t++)
            acc += al[t] * g_x2[((size_t)b*TT + t)*H2 + c];
        g_pooled[b*H2 + c] = acc;
    }
}

// ---------------- final: out = [pooled, 1] @ W ----------------
__global__ void k_final(const float* __restrict__ W, float* __restrict__ out) {
    __shared__ float ps[H2];
    int b = blockIdx.x, tid = threadIdx.x;
    for (int c = tid; c < H2; c += 256) ps[c] = g_pooled[b*H2 + c];
    __syncthreads();
    for (int j = tid; j < COUT; j += 256) {
        float acc = W[(size_t)H2*COUT + j];     // bias row (padded 1)
        for (int c = 0; c < H2; c++)
            acc += ps[c] * W[(size_t)c*COUT + j];
        out[b*COUT + j] = acc;
    }
}

// ---------------- host orchestration ----------------
// Launch #4 must be the first k_stepgemm (ncu -s 5 -c 1 lands on my launch #4):
//   #1 k_bn1, #2 k_sgemm(layer0), #3 k_lnzero(layer0, also zeroes h/c), #4 k_stepgemm.
extern "C" void kernel_launch(void* const* d_in, const int* in_sizes, int n_in,
                              void* d_out, int out_size) {
    const float* emb  = (const float*)d_in[0];
    const float* bn1g = (const float*)d_in[1];
    const float* bn1b = (const float*)d_in[2];
    const float* bn2g = (const float*)d_in[3];
    const float* bn2b = (const float*)d_in[4];
    const float* wih0 = (const float*)d_in[5];
    const float* whh0 = (const float*)d_in[6];
    const float* lng0 = (const float*)d_in[7];
    const float* lnb0 = (const float*)d_in[8];
    const float* wih1 = (const float*)d_in[9];
    const float* whh1 = (const float*)d_in[10];
    const float* lng1 = (const float*)d_in[11];
    const float* lnb1 = (const float*)d_in[12];
    const float* wom  = (const float*)d_in[13];
    const float* bom  = (const float*)d_in[14];
    const float* uom  = (const float*)d_in[15];
    const float* Wm   = (const float*)d_in[16];
    float* out = (float*)d_out;

    float *p_x0, *p_h0, *p_h1;
    cudaGetSymbolAddress((void**)&p_x0, g_x0);
    cudaGetSymbolAddress((void**)&p_h0, g_hout0);
    cudaGetSymbolAddress((void**)&p_h1, g_hout1);

    k_bn1<<<VV, 256>>>(emb, bn1g, bn1b);                              // #1

    // ---- layer 0 ----
    k_sgemm<<<dim3(16, 64, 2), 256>>>(p_x0, wih0, VV, (long)G4*VV);   // #2
    k_lnzero<<<2*NROW, 256>>>(lng0, lnb0);                            // #3 (LN + zero h/c)
    for (int s = 0; s < TT; s++) {
        k_stepgemm<<<dim3(32, 4, 2), 256>>>(whh0);                    // #4 on s==0 <- profiled
        k_steppoint<<<128, 256>>>(lng0, lnb0, p_h0, s);
    }

    // ---- layer 1 ----
    k_sgemm<<<dim3(16, 64, 2), 256>>>(p_h0, wih1, H2, (long)G4*H2);
    k_lnzero<<<2*NROW, 256>>>(lng1, lnb1);
    for (int s = 0; s < TT; s++) {
        k_stepgemm<<<dim3(32, 4, 2), 256>>>(whh1);
        k_steppoint<<<128, 256>>>(lng1, lnb1, p_h1, s);
    }

    k_bn2<<<H2, 256>>>(bn2g, bn2b);
    k_att<<<NROW/4, 256>>>(wom, bom, uom);
    k_softpool<<<BB, 256>>>();
    k_final<<<BB, 256>>>(Wm, out);
}